// round 2
// baseline (speedup 1.0000x reference)
#include <cuda_runtime.h>

// Problem constants
constexpr int NB  = 8;      // batch
constexpr int NC  = 512;    // channels
constexpr int NHW = 4096;   // tokens (64*64)
constexpr int NG  = 32;     // groups
constexpr int CPG = NC / NG;      // 16 channels per group
constexpr float EPS = 1e-5f;
constexpr float ATTN_SCALE = 0.04419417382415922f;  // 512^-0.5

// ---------------------------------------------------------------------------
// Scratch (device globals: allocation-free, graph-capture safe)
// ---------------------------------------------------------------------------
__device__ float g_t[(size_t)NB * NHW * NC];     // groupnormed tokens (B,HW,C)
__device__ float g_q[(size_t)NB * NHW * NC];
__device__ float g_k[(size_t)NB * NHW * NC];
__device__ float g_v[(size_t)NB * NHW * NC];
__device__ float g_o[(size_t)NB * NHW * NC];     // attn output tokens
__device__ float g_s[(size_t)NB * NHW * NHW];    // scores / attn (B,HW,HW)
__device__ float g_mean[NB * NG];
__device__ float g_rstd[NB * NG];

// ---------------------------------------------------------------------------
// 1) GroupNorm statistics: one block per (b, g); reduce CPG*HW = 65536 elems.
// ---------------------------------------------------------------------------
__global__ __launch_bounds__(256) void gn_stats_kernel(const float* __restrict__ x) {
    const int bg = blockIdx.x;
    const float* p = x + (size_t)bg * CPG * NHW;
    float s = 0.f, ss = 0.f;
    for (int i = threadIdx.x; i < CPG * NHW; i += 256) {
        float v = p[i];
        s += v;
        ss += v * v;
    }
    __shared__ float rs[256], rss[256];
    rs[threadIdx.x] = s;
    rss[threadIdx.x] = ss;
    __syncthreads();
    for (int o = 128; o > 0; o >>= 1) {
        if (threadIdx.x < o) {
            rs[threadIdx.x]  += rs[threadIdx.x + o];
            rss[threadIdx.x] += rss[threadIdx.x + o];
        }
        __syncthreads();
    }
    if (threadIdx.x == 0) {
        const float inv_n = 1.f / (float)(CPG * NHW);
        float m = rs[0] * inv_n;
        float var = rss[0] * inv_n - m * m;
        g_mean[bg] = m;
        g_rstd[bg] = rsqrtf(var + EPS);
    }
}

// ---------------------------------------------------------------------------
// 2) Normalize + affine + transpose (B,C,HW) -> token-major (B,HW,C).
// ---------------------------------------------------------------------------
__global__ __launch_bounds__(256) void gn_apply_transpose_kernel(
    const float* __restrict__ x,
    const float* __restrict__ gamma,
    const float* __restrict__ beta)
{
    __shared__ float tile[32][33];
    const int b  = blockIdx.z;
    const int p0 = blockIdx.x * 32;
    const int c0 = blockIdx.y * 32;
    const int tx = threadIdx.x, ty = threadIdx.y;

    #pragma unroll
    for (int i = ty; i < 32; i += 8) {
        const int c = c0 + i;
        tile[i][tx] = x[((size_t)b * NC + c) * NHW + p0 + tx];
    }
    __syncthreads();

    const int c = c0 + tx;
    const float ga = gamma[c];
    const float be = beta[c];
    const float mean = g_mean[b * NG + c / CPG];
    const float rstd = g_rstd[b * NG + c / CPG];
    #pragma unroll
    for (int i = ty; i < 32; i += 8) {
        const int p = p0 + i;
        g_t[((size_t)b * NHW + p) * NC + c] = (tile[tx][i] - mean) * rstd * ga + be;
    }
}

// ---------------------------------------------------------------------------
// 3) Tiled SGEMM, 128x128 block tile, BK=8, 256 threads, 8x8 micro-tile,
//    double-buffered shared memory (one __syncthreads per K-slab).
//    TB=true : C = A(MxK) @ B(NxK)^T    (ldb = K)
//    TB=false: C = A(MxK) @ B(KxN)      (ldb = N)
//    MODE 0: C[m,n] = acc + bias[n]                        (projections)
//    MODE 1: C[m,n] = acc * alpha                          (scores / attn@V)
//    MODE 2: out[b,c,hw] = acc + bias[n] + resid[b,c,hw]   (o-proj + residual)
//    All dims divisible by tile sizes (128 | M,N; 8 | K) — no guards.
// ---------------------------------------------------------------------------
template <bool TB, int MODE>
__global__ __launch_bounds__(256) void gemm128_kernel(
    const float* __restrict__ A,
    const float* __restrict__ Bm,
    const float* __restrict__ bias,
    float* __restrict__ Cm,
    int M, int N, int K,
    size_t strideA, size_t strideB, size_t strideC,
    float alpha,
    const float* __restrict__ resid)
{
    const int bz = blockIdx.z;
    A  += (size_t)bz * strideA;
    Bm += (size_t)bz * strideB;

    __shared__ float As[2][8][128];
    __shared__ float Bs[2][8][128];

    const int tid = threadIdx.x;
    const int tx = tid & 15;          // n-dim thread coord (0..15)
    const int ty = tid >> 4;          // m-dim thread coord (0..15)
    const int m0 = blockIdx.y * 128;
    const int n0 = blockIdx.x * 128;

    // Global-load index split
    const int lr  = tid >> 1;         // 0..127 : row within 128-row tile
    const int lc  = (tid & 1) * 4;    // 0 or 4 : k offset (float4 along K)
    const int nr  = tid >> 5;         // 0..7   : k row (NN B tile)
    const int ncl = (tid & 31) * 4;   // 0..124 : n offset (NN B tile)

    float4 pa, pb;

    // Prefetch tile 0
    pa = *(const float4*)(A + (size_t)(m0 + lr) * K + lc);
    if (TB) pb = *(const float4*)(Bm + (size_t)(n0 + lr) * K + lc);
    else    pb = *(const float4*)(Bm + (size_t)nr * N + n0 + ncl);

    As[0][lc + 0][lr] = pa.x;
    As[0][lc + 1][lr] = pa.y;
    As[0][lc + 2][lr] = pa.z;
    As[0][lc + 3][lr] = pa.w;
    if (TB) {
        Bs[0][lc + 0][lr] = pb.x;
        Bs[0][lc + 1][lr] = pb.y;
        Bs[0][lc + 2][lr] = pb.z;
        Bs[0][lc + 3][lr] = pb.w;
    } else {
        *(float4*)&Bs[0][nr][ncl] = pb;
    }
    __syncthreads();

    float acc[8][8] = {};
    const int nk = K >> 3;

    for (int kt = 0; kt < nk; kt++) {
        const int cur = kt & 1;
        const bool has_next = (kt + 1) < nk;

        // Prefetch next K-slab from global into registers
        if (has_next) {
            const int k0 = (kt + 1) << 3;
            pa = *(const float4*)(A + (size_t)(m0 + lr) * K + k0 + lc);
            if (TB) pb = *(const float4*)(Bm + (size_t)(n0 + lr) * K + k0 + lc);
            else    pb = *(const float4*)(Bm + (size_t)(k0 + nr) * N + n0 + ncl);
        }

        // Compute on current buffer
        #pragma unroll
        for (int k = 0; k < 8; k++) {
            float ar[8], br[8];
            *(float4*)&ar[0] = *(const float4*)&As[cur][k][ty * 8];
            *(float4*)&ar[4] = *(const float4*)&As[cur][k][ty * 8 + 4];
            *(float4*)&br[0] = *(const float4*)&Bs[cur][k][tx * 8];
            *(float4*)&br[4] = *(const float4*)&Bs[cur][k][tx * 8 + 4];
            #pragma unroll
            for (int i = 0; i < 8; i++)
                #pragma unroll
                for (int j = 0; j < 8; j++)
                    acc[i][j] += ar[i] * br[j];
        }

        // Stage next slab into the other buffer
        if (has_next) {
            const int nxt = cur ^ 1;
            As[nxt][lc + 0][lr] = pa.x;
            As[nxt][lc + 1][lr] = pa.y;
            As[nxt][lc + 2][lr] = pa.z;
            As[nxt][lc + 3][lr] = pa.w;
            if (TB) {
                Bs[nxt][lc + 0][lr] = pb.x;
                Bs[nxt][lc + 1][lr] = pb.y;
                Bs[nxt][lc + 2][lr] = pb.z;
                Bs[nxt][lc + 3][lr] = pb.w;
            } else {
                *(float4*)&Bs[nxt][nr][ncl] = pb;
            }
            __syncthreads();
        }
    }

    if (MODE != 2) Cm += (size_t)bz * strideC;

    #pragma unroll
    for (int i = 0; i < 8; i++) {
        const int m = m0 + ty * 8 + i;
        #pragma unroll
        for (int j = 0; j < 8; j++) {
            const int n = n0 + tx * 8 + j;
            if (MODE == 0) {
                Cm[(size_t)m * N + n] = acc[i][j] + bias[n];
            } else if (MODE == 1) {
                Cm[(size_t)m * N + n] = acc[i][j] * alpha;
            } else {
                const int b_ = m >> 12;        // 4096 tokens per batch
                const int p_ = m & 4095;
                const size_t idx = ((size_t)b_ * NC + n) * (size_t)NHW + p_;
                Cm[idx] = acc[i][j] + bias[n] + resid[idx];
            }
        }
    }
}

// ---------------------------------------------------------------------------
// 4) Row softmax over 4096 elements. One block (256 threads) per row.
// ---------------------------------------------------------------------------
__global__ __launch_bounds__(256) void softmax4096_kernel(float* __restrict__ s) {
    const size_t row = blockIdx.x;
    float* p = s + row * (size_t)NHW;

    __shared__ float buf[NHW];
    __shared__ float red[256];

    float mx = -1e30f;
    for (int i = threadIdx.x; i < NHW; i += 256) {
        float v = p[i];
        buf[i] = v;
        mx = fmaxf(mx, v);
    }
    red[threadIdx.x] = mx;
    __syncthreads();
    for (int o = 128; o > 0; o >>= 1) {
        if (threadIdx.x < o) red[threadIdx.x] = fmaxf(red[threadIdx.x], red[threadIdx.x + o]);
        __syncthreads();
    }
    mx = red[0];
    __syncthreads();

    float sum = 0.f;
    for (int i = threadIdx.x; i < NHW; i += 256) {
        float e = __expf(buf[i] - mx);
        buf[i] = e;
        sum += e;
    }
    red[threadIdx.x] = sum;
    __syncthreads();
    for (int o = 128; o > 0; o >>= 1) {
        if (threadIdx.x < o) red[threadIdx.x] += red[threadIdx.x + o];
        __syncthreads();
    }
    const float inv = 1.f / red[0];
    __syncthreads();

    for (int i = threadIdx.x; i < NHW; i += 256)
        p[i] = buf[i] * inv;
}

// ---------------------------------------------------------------------------
// Launch
// ---------------------------------------------------------------------------
extern "C" void kernel_launch(void* const* d_in, const int* in_sizes, int n_in,
                              void* d_out, int out_size)
{
    const float* x   = (const float*)d_in[0];
    const float* gnw = (const float*)d_in[1];
    const float* gnb = (const float*)d_in[2];
    const float* wq  = (const float*)d_in[3];
    const float* bq  = (const float*)d_in[4];
    const float* wk  = (const float*)d_in[5];
    const float* bk  = (const float*)d_in[6];
    const float* wv  = (const float*)d_in[7];
    const float* bv  = (const float*)d_in[8];
    const float* wo  = (const float*)d_in[9];
    const float* bo  = (const float*)d_in[10];
    float* out = (float*)d_out;

    float *t, *q, *k, *v, *o, *s;
    cudaGetSymbolAddress((void**)&t, g_t);
    cudaGetSymbolAddress((void**)&q, g_q);
    cudaGetSymbolAddress((void**)&k, g_k);
    cudaGetSymbolAddress((void**)&v, g_v);
    cudaGetSymbolAddress((void**)&o, g_o);
    cudaGetSymbolAddress((void**)&s, g_s);

    const size_t tokStride = (size_t)NHW * NC;       // per-batch token-tensor stride
    const size_t scoStride = (size_t)NHW * NHW;      // per-batch score stride

    // 1) GroupNorm stats
    gn_stats_kernel<<<NB * NG, 256>>>(x);

    // 2) Normalize + transpose to (B,HW,C)
    gn_apply_transpose_kernel<<<dim3(NHW / 32, NC / 32, NB), dim3(32, 8)>>>(x, gnw, gnb);

    // 3) Q, K, V projections: (32768 x 512) = t @ W^T + b
    gemm128_kernel<true, 0><<<dim3(NC / 128, (NB * NHW) / 128), 256>>>(
        t, wq, bq, q, NB * NHW, NC, NC, 0, 0, 0, 1.f, nullptr);
    gemm128_kernel<true, 0><<<dim3(NC / 128, (NB * NHW) / 128), 256>>>(
        t, wk, bk, k, NB * NHW, NC, NC, 0, 0, 0, 1.f, nullptr);
    gemm128_kernel<true, 0><<<dim3(NC / 128, (NB * NHW) / 128), 256>>>(
        t, wv, bv, v, NB * NHW, NC, NC, 0, 0, 0, 1.f, nullptr);

    // 4) scores = scale * q @ k^T, per batch (4096 x 4096, K = 512)
    gemm128_kernel<true, 1><<<dim3(NHW / 128, NHW / 128, NB), 256>>>(
        q, k, nullptr, s, NHW, NHW, NC, tokStride, tokStride, scoStride,
        ATTN_SCALE, nullptr);

    // 5) softmax over rows
    softmax4096_kernel<<<NB * NHW, 256>>>(s);

    // 6) o = attn @ v, per batch (4096 x 512, K = 4096), NN layout
    gemm128_kernel<false, 1><<<dim3(NC / 128, NHW / 128, NB), 256>>>(
        s, v, nullptr, o, NHW, NC, NHW, scoStride, tokStride, tokStride,
        1.f, nullptr);

    // 7) out = o @ wo^T + bo, transposed back to (B,C,H,W), + residual x
    gemm128_kernel<true, 2><<<dim3(NC / 128, (NB * NHW) / 128), 256>>>(
        o, wo, bo, out, NB * NHW, NC, NC, 0, 0, 0, 1.f, x);
}

// round 3
// speedup vs baseline: 2.3902x; 2.3902x over previous
#include <cuda_runtime.h>
#include <cuda_bf16.h>

using bf16 = __nv_bfloat16;

// Problem constants
constexpr int NB  = 8;
constexpr int NC  = 512;
constexpr int NHW = 4096;
constexpr int NG  = 32;
constexpr int CPG = NC / NG;            // 16
constexpr int NTOK = NB * NHW;          // 32768
constexpr float EPS = 1e-5f;
constexpr float ATTN_SCALE = 0.04419417382415922f;  // 512^-0.5

// ---------------------------------------------------------------------------
// Scratch (device globals)
// ---------------------------------------------------------------------------
__device__ bf16 g_thi[(size_t)NTOK * NC], g_tlo[(size_t)NTOK * NC];
__device__ bf16 g_qhi[(size_t)NTOK * NC], g_qlo[(size_t)NTOK * NC];
__device__ bf16 g_khi[(size_t)NTOK * NC], g_klo[(size_t)NTOK * NC];
__device__ float g_vf[(size_t)NTOK * NC];
__device__ bf16 g_vthi[(size_t)NTOK * NC], g_vtlo[(size_t)NTOK * NC]; // (B, C, HW)
__device__ bf16 g_ohi[(size_t)NTOK * NC], g_olo[(size_t)NTOK * NC];
__device__ float g_o2[(size_t)NTOK * NC];
__device__ float g_s[(size_t)NB * NHW * NHW];
__device__ bf16 g_phi[(size_t)NB * NHW * NHW], g_plo[(size_t)NB * NHW * NHW];
__device__ bf16 g_whi[(size_t)4 * NC * NC], g_wlo[(size_t)4 * NC * NC];
__device__ float g_mean[NB * NG], g_rstd[NB * NG];

// ---------------------------------------------------------------------------
// Helpers
// ---------------------------------------------------------------------------
__device__ __forceinline__ void split1(bf16* hi, bf16* lo, size_t idx, float v) {
    bf16 h = __float2bfloat16(v);
    hi[idx] = h;
    lo[idx] = __float2bfloat16(v - __bfloat162float(h));
}

__device__ __forceinline__ void split2(float v0, float v1,
                                       bf16* __restrict__ hi, bf16* __restrict__ lo,
                                       size_t idx) {
    bf16 h0 = __float2bfloat16(v0);
    bf16 h1 = __float2bfloat16(v1);
    __nv_bfloat162 h2; h2.x = h0; h2.y = h1;
    *(__nv_bfloat162*)(hi + idx) = h2;
    __nv_bfloat162 l2;
    l2.x = __float2bfloat16(v0 - __bfloat162float(h0));
    l2.y = __float2bfloat16(v1 - __bfloat162float(h1));
    *(__nv_bfloat162*)(lo + idx) = l2;
}

__device__ __forceinline__ void ldsm4(unsigned& r0, unsigned& r1, unsigned& r2, unsigned& r3,
                                      unsigned addr) {
    asm volatile("ldmatrix.sync.aligned.m8n8.x4.shared.b16 {%0,%1,%2,%3}, [%4];"
                 : "=r"(r0), "=r"(r1), "=r"(r2), "=r"(r3) : "r"(addr));
}

__device__ __forceinline__ void mma_bf16(float* d, const unsigned* a, const unsigned* b) {
    asm volatile("mma.sync.aligned.m16n8k16.row.col.f32.bf16.bf16.f32 "
                 "{%0,%1,%2,%3}, {%4,%5,%6,%7}, {%8,%9}, {%0,%1,%2,%3};"
                 : "+f"(d[0]), "+f"(d[1]), "+f"(d[2]), "+f"(d[3])
                 : "r"(a[0]), "r"(a[1]), "r"(a[2]), "r"(a[3]), "r"(b[0]), "r"(b[1]));
}

// ---------------------------------------------------------------------------
// 1) GroupNorm statistics
// ---------------------------------------------------------------------------
__global__ __launch_bounds__(256) void gn_stats_kernel(const float* __restrict__ x) {
    const int bg = blockIdx.x;
    const float* p = x + (size_t)bg * CPG * NHW;
    float s = 0.f, ss = 0.f;
    for (int i = threadIdx.x; i < CPG * NHW; i += 256) {
        float v = p[i];
        s += v; ss += v * v;
    }
    __shared__ float rs[256], rss[256];
    rs[threadIdx.x] = s; rss[threadIdx.x] = ss;
    __syncthreads();
    for (int o = 128; o > 0; o >>= 1) {
        if (threadIdx.x < o) { rs[threadIdx.x] += rs[threadIdx.x + o]; rss[threadIdx.x] += rss[threadIdx.x + o]; }
        __syncthreads();
    }
    if (threadIdx.x == 0) {
        const float inv_n = 1.f / (float)(CPG * NHW);
        float m = rs[0] * inv_n;
        float var = rss[0] * inv_n - m * m;
        g_mean[bg] = m;
        g_rstd[bg] = rsqrtf(var + EPS);
    }
}

// ---------------------------------------------------------------------------
// 2) Normalize + affine + transpose -> token-major bf16 hi/lo
// ---------------------------------------------------------------------------
__global__ __launch_bounds__(256) void gn_apply_transpose_kernel(
    const float* __restrict__ x,
    const float* __restrict__ gamma,
    const float* __restrict__ beta)
{
    __shared__ float tile[32][33];
    const int b  = blockIdx.z;
    const int p0 = blockIdx.x * 32;
    const int c0 = blockIdx.y * 32;
    const int tx = threadIdx.x, ty = threadIdx.y;

    #pragma unroll
    for (int i = ty; i < 32; i += 8)
        tile[i][tx] = x[((size_t)b * NC + c0 + i) * NHW + p0 + tx];
    __syncthreads();

    const int c = c0 + tx;
    const float ga = gamma[c];
    const float be = beta[c];
    const float mean = g_mean[b * NG + c / CPG];
    const float rstd = g_rstd[b * NG + c / CPG];
    #pragma unroll
    for (int i = ty; i < 32; i += 8) {
        const int p = p0 + i;
        float v = (tile[tx][i] - mean) * rstd * ga + be;
        split1(g_thi, g_tlo, ((size_t)b * NHW + p) * NC + c, v);
    }
}

// ---------------------------------------------------------------------------
// 3) Weight fp32 -> bf16 hi/lo
// ---------------------------------------------------------------------------
__global__ __launch_bounds__(256) void convw_kernel(const float* __restrict__ w,
                                                    bf16* __restrict__ hi,
                                                    bf16* __restrict__ lo) {
    int i = blockIdx.x * 256 + threadIdx.x;
    split1(hi, lo, i, w[i]);
}

// ---------------------------------------------------------------------------
// 4) bf16 split-precision GEMM:  C = A @ B^T  (A: MxK, B: NxK, both row-major)
//    3 MMA passes: Ahi*Bhi + Alo*Bhi + Ahi*Blo  (fp32 accumulate)
//    Block 128x128x32, 8 warps (warp tile 64x32), mma.sync m16n8k16.
//    MODE 0: Ohi/Olo[m*N+n]      = split(acc + bias[n])        (q/k proj)
//    MODE 1: f32out[m*N+n]       = acc + bias[n]               (v proj, o-proj)
//    MODE 2: f32out[z*sC+m*N+n]  = acc * alpha                 (scores)
//    MODE 3: Ohi/Olo[z*sC+m*N+n] = split(acc)                  (attn @ V)
// ---------------------------------------------------------------------------
constexpr int BM = 128, BN = 128, BK = 32, SST = 40;

template <int MODE>
__global__ __launch_bounds__(256, 1) void bgemm_kernel(
    const bf16* __restrict__ Ahi, const bf16* __restrict__ Alo,
    const bf16* __restrict__ Bhi, const bf16* __restrict__ Blo,
    const float* __restrict__ bias,
    float* __restrict__ f32out, bf16* __restrict__ Ohi, bf16* __restrict__ Olo,
    int N, int K, size_t sA, size_t sB, size_t sC, float alpha)
{
    const int bz = blockIdx.z;
    Ahi += bz * sA; Alo += bz * sA;
    Bhi += bz * sB; Blo += bz * sB;

    const int m0 = blockIdx.y * BM;
    const int n0 = blockIdx.x * BN;
    const int tid = threadIdx.x;
    const int lane = tid & 31;
    const int wid = tid >> 5;
    const int wm = (wid >> 2) * 64;     // 0 / 64
    const int wn = (wid & 3) * 32;      // 0..96

    __shared__ bf16 sAh[BM * SST], sAl[BM * SST], sBh[BM * SST], sBl[BM * SST];

    // Staging: each thread moves 2 uint4 (16 bf16) per tile per iter.
    const int sr = tid >> 2;            // 0..63
    const int sc = (tid & 3) * 8;       // 0,8,16,24
    const bf16* pAh0 = Ahi + (size_t)m0 * K;
    const bf16* pAl0 = Alo + (size_t)m0 * K;
    const bf16* pBh0 = Bhi + (size_t)n0 * K;
    const bf16* pBl0 = Blo + (size_t)n0 * K;

    uint4 ra_h[2], ra_l[2], rb_h[2], rb_l[2];

    // initial prefetch (k0 = 0)
    #pragma unroll
    for (int u = 0; u < 2; u++) {
        size_t off = (size_t)(sr + u * 64) * K + sc;
        ra_h[u] = *(const uint4*)(pAh0 + off);
        ra_l[u] = *(const uint4*)(pAl0 + off);
        rb_h[u] = *(const uint4*)(pBh0 + off);
        rb_l[u] = *(const uint4*)(pBl0 + off);
    }

    const unsigned base_ah = (unsigned)__cvta_generic_to_shared(sAh);
    const unsigned base_al = (unsigned)__cvta_generic_to_shared(sAl);
    const unsigned base_bh = (unsigned)__cvta_generic_to_shared(sBh);
    const unsigned base_bl = (unsigned)__cvta_generic_to_shared(sBl);

    float acc[4][4][4] = {};

    const int nk = K / BK;
    for (int kt = 0; kt < nk; kt++) {
        // store prefetched slab to smem
        #pragma unroll
        for (int u = 0; u < 2; u++) {
            int so = (sr + u * 64) * SST + sc;
            *(uint4*)&sAh[so] = ra_h[u];
            *(uint4*)&sAl[so] = ra_l[u];
            *(uint4*)&sBh[so] = rb_h[u];
            *(uint4*)&sBl[so] = rb_l[u];
        }
        __syncthreads();

        // prefetch next slab
        if (kt + 1 < nk) {
            const int k0 = (kt + 1) * BK;
            #pragma unroll
            for (int u = 0; u < 2; u++) {
                size_t off = (size_t)(sr + u * 64) * K + k0 + sc;
                ra_h[u] = *(const uint4*)(pAh0 + off);
                ra_l[u] = *(const uint4*)(pAl0 + off);
                rb_h[u] = *(const uint4*)(pBh0 + off);
                rb_l[u] = *(const uint4*)(pBl0 + off);
            }
        }

        // compute 2 k16 steps
        #pragma unroll
        for (int kk = 0; kk < BK; kk += 16) {
            unsigned ah[4][4], al[4][4], bh[4][2], bl[4][2];

            const int arow = wm + (lane & 15);
            const int acol = kk + ((lane >> 4) << 3);
            #pragma unroll
            for (int i = 0; i < 4; i++) {
                unsigned off = (unsigned)(((arow + i * 16) * SST + acol) * 2);
                ldsm4(ah[i][0], ah[i][1], ah[i][2], ah[i][3], base_ah + off);
                ldsm4(al[i][0], al[i][1], al[i][2], al[i][3], base_al + off);
            }

            const int brow = wn + ((lane >> 4) << 3) + (lane & 7);
            const int bcol = kk + (((lane >> 3) & 1) << 3);
            #pragma unroll
            for (int jp = 0; jp < 2; jp++) {
                unsigned off = (unsigned)(((brow + jp * 16) * SST + bcol) * 2);
                ldsm4(bh[2 * jp][0], bh[2 * jp][1], bh[2 * jp + 1][0], bh[2 * jp + 1][1], base_bh + off);
                ldsm4(bl[2 * jp][0], bl[2 * jp][1], bl[2 * jp + 1][0], bl[2 * jp + 1][1], base_bl + off);
            }

            #pragma unroll
            for (int i = 0; i < 4; i++)
                #pragma unroll
                for (int j = 0; j < 4; j++) {
                    mma_bf16(acc[i][j], ah[i], bh[j]);
                    mma_bf16(acc[i][j], al[i], bh[j]);
                    mma_bf16(acc[i][j], ah[i], bl[j]);
                }
        }
        __syncthreads();
    }

    // Epilogue. Fragment (i,j): rows (wm+i*16+lane/4, +8), cols (wn+j*8+(lane%4)*2, +1)
    #pragma unroll
    for (int i = 0; i < 4; i++) {
        const int row0 = m0 + wm + i * 16 + (lane >> 2);
        #pragma unroll
        for (int j = 0; j < 4; j++) {
            const int col = n0 + wn + j * 8 + (lane & 3) * 2;
            float* a = acc[i][j];
            if (MODE == 0) {
                const float b0 = bias[col], b1 = bias[col + 1];
                split2(a[0] + b0, a[1] + b1, Ohi, Olo, (size_t)row0 * N + col);
                split2(a[2] + b0, a[3] + b1, Ohi, Olo, (size_t)(row0 + 8) * N + col);
            } else if (MODE == 1) {
                const float b0 = bias[col], b1 = bias[col + 1];
                *(float2*)&f32out[(size_t)row0 * N + col]       = make_float2(a[0] + b0, a[1] + b1);
                *(float2*)&f32out[(size_t)(row0 + 8) * N + col] = make_float2(a[2] + b0, a[3] + b1);
            } else if (MODE == 2) {
                float* o = f32out + (size_t)bz * sC;
                *(float2*)&o[(size_t)row0 * N + col]       = make_float2(a[0] * alpha, a[1] * alpha);
                *(float2*)&o[(size_t)(row0 + 8) * N + col] = make_float2(a[2] * alpha, a[3] * alpha);
            } else {
                bf16* oh = Ohi + (size_t)bz * sC;
                bf16* ol = Olo + (size_t)bz * sC;
                split2(a[0], a[1], oh, ol, (size_t)row0 * N + col);
                split2(a[2], a[3], oh, ol, (size_t)(row0 + 8) * N + col);
            }
        }
    }
}

// ---------------------------------------------------------------------------
// 5) v (token-major fp32) -> v^T (channel-major bf16 hi/lo), per batch
// ---------------------------------------------------------------------------
__global__ __launch_bounds__(256) void vtrans_kernel() {
    __shared__ float tile[32][33];
    const int b = blockIdx.z, p0 = blockIdx.x * 32, c0 = blockIdx.y * 32;
    const int tx = threadIdx.x, ty = threadIdx.y;
    #pragma unroll
    for (int i = ty; i < 32; i += 8)
        tile[i][tx] = g_vf[((size_t)b * NHW + p0 + i) * NC + c0 + tx];
    __syncthreads();
    #pragma unroll
    for (int i = ty; i < 32; i += 8) {
        size_t idx = ((size_t)(b * NC + c0 + i)) * NHW + p0 + tx;
        split1(g_vthi, g_vtlo, idx, tile[tx][i]);
    }
}

// ---------------------------------------------------------------------------
// 6) Row softmax over 4096; write bf16 hi/lo attn
// ---------------------------------------------------------------------------
__global__ __launch_bounds__(256) void softmax4096_kernel() {
    const size_t row = blockIdx.x;
    const float* p = g_s + row * (size_t)NHW;

    __shared__ float buf[NHW];
    __shared__ float red[256];

    float mx = -1e30f;
    for (int i = threadIdx.x; i < NHW; i += 256) {
        float v = p[i];
        buf[i] = v;
        mx = fmaxf(mx, v);
    }
    red[threadIdx.x] = mx;
    __syncthreads();
    for (int o = 128; o > 0; o >>= 1) {
        if (threadIdx.x < o) red[threadIdx.x] = fmaxf(red[threadIdx.x], red[threadIdx.x + o]);
        __syncthreads();
    }
    mx = red[0];
    __syncthreads();

    float sum = 0.f;
    for (int i = threadIdx.x; i < NHW; i += 256) {
        float e = __expf(buf[i] - mx);
        buf[i] = e;
        sum += e;
    }
    red[threadIdx.x] = sum;
    __syncthreads();
    for (int o = 128; o > 0; o >>= 1) {
        if (threadIdx.x < o) red[threadIdx.x] += red[threadIdx.x + o];
        __syncthreads();
    }
    const float inv = 1.f / red[0];
    __syncthreads();

    for (int i = threadIdx.x; i < NHW; i += 256)
        split1(g_phi, g_plo, row * (size_t)NHW + i, buf[i] * inv);
}

// ---------------------------------------------------------------------------
// 7) Final: out(B,C,HW) = transpose(o2 token-major) + x   (bias added in GEMM)
// ---------------------------------------------------------------------------
__global__ __launch_bounds__(256) void final_kernel(const float* __restrict__ x,
                                                    float* __restrict__ out) {
    __shared__ float tile[32][33];
    const int b = blockIdx.z, p0 = blockIdx.x * 32, c0 = blockIdx.y * 32;
    const int tx = threadIdx.x, ty = threadIdx.y;
    #pragma unroll
    for (int i = ty; i < 32; i += 8)
        tile[i][tx] = g_o2[((size_t)b * NHW + p0 + i) * NC + c0 + tx];
    __syncthreads();
    #pragma unroll
    for (int i = ty; i < 32; i += 8) {
        size_t idx = ((size_t)(b * NC + c0 + i)) * NHW + p0 + tx;
        out[idx] = tile[tx][i] + x[idx];
    }
}

// ---------------------------------------------------------------------------
// Launch
// ---------------------------------------------------------------------------
extern "C" void kernel_launch(void* const* d_in, const int* in_sizes, int n_in,
                              void* d_out, int out_size)
{
    const float* x   = (const float*)d_in[0];
    const float* gnw = (const float*)d_in[1];
    const float* gnb = (const float*)d_in[2];
    const float* wq  = (const float*)d_in[3];
    const float* bq  = (const float*)d_in[4];
    const float* wk  = (const float*)d_in[5];
    const float* bk  = (const float*)d_in[6];
    const float* wv  = (const float*)d_in[7];
    const float* bv  = (const float*)d_in[8];
    const float* wo  = (const float*)d_in[9];
    const float* bo  = (const float*)d_in[10];
    float* out = (float*)d_out;

    bf16 *thi, *tlo, *qhi, *qlo, *khi, *klo, *vthi, *vtlo, *ohi, *olo, *phi, *plo, *whi, *wlo;
    float *vf, *o2, *s;
    cudaGetSymbolAddress((void**)&thi, g_thi);   cudaGetSymbolAddress((void**)&tlo, g_tlo);
    cudaGetSymbolAddress((void**)&qhi, g_qhi);   cudaGetSymbolAddress((void**)&qlo, g_qlo);
    cudaGetSymbolAddress((void**)&khi, g_khi);   cudaGetSymbolAddress((void**)&klo, g_klo);
    cudaGetSymbolAddress((void**)&vthi, g_vthi); cudaGetSymbolAddress((void**)&vtlo, g_vtlo);
    cudaGetSymbolAddress((void**)&ohi, g_ohi);   cudaGetSymbolAddress((void**)&olo, g_olo);
    cudaGetSymbolAddress((void**)&phi, g_phi);   cudaGetSymbolAddress((void**)&plo, g_plo);
    cudaGetSymbolAddress((void**)&whi, g_whi);   cudaGetSymbolAddress((void**)&wlo, g_wlo);
    cudaGetSymbolAddress((void**)&vf, g_vf);
    cudaGetSymbolAddress((void**)&o2, g_o2);
    cudaGetSymbolAddress((void**)&s, g_s);

    const size_t tokStride = (size_t)NHW * NC;       // per-batch token stride
    const size_t scoStride = (size_t)NHW * NHW;      // per-batch score stride
    const size_t WSZ = (size_t)NC * NC;

    // 1) GroupNorm stats + apply (-> t hi/lo, token-major)
    gn_stats_kernel<<<NB * NG, 256>>>(x);
    gn_apply_transpose_kernel<<<dim3(NHW / 32, NC / 32, NB), dim3(32, 8)>>>(x, gnw, gnb);

    // 2) Weight splits
    convw_kernel<<<WSZ / 256, 256>>>(wq, whi + 0 * WSZ, wlo + 0 * WSZ);
    convw_kernel<<<WSZ / 256, 256>>>(wk, whi + 1 * WSZ, wlo + 1 * WSZ);
    convw_kernel<<<WSZ / 256, 256>>>(wv, whi + 2 * WSZ, wlo + 2 * WSZ);
    convw_kernel<<<WSZ / 256, 256>>>(wo, whi + 3 * WSZ, wlo + 3 * WSZ);

    // 3) Projections (M=32768, N=512, K=512)
    bgemm_kernel<0><<<dim3(NC / BN, NTOK / BM), 256>>>(
        thi, tlo, whi + 0 * WSZ, wlo + 0 * WSZ, bq, nullptr, qhi, qlo, NC, NC, 0, 0, 0, 1.f);
    bgemm_kernel<0><<<dim3(NC / BN, NTOK / BM), 256>>>(
        thi, tlo, whi + 1 * WSZ, wlo + 1 * WSZ, bk, nullptr, khi, klo, NC, NC, 0, 0, 0, 1.f);
    bgemm_kernel<1><<<dim3(NC / BN, NTOK / BM), 256>>>(
        thi, tlo, whi + 2 * WSZ, wlo + 2 * WSZ, bv, vf, nullptr, nullptr, NC, NC, 0, 0, 0, 1.f);

    // 4) v -> v^T hi/lo
    vtrans_kernel<<<dim3(NHW / 32, NC / 32, NB), dim3(32, 8)>>>();

    // 5) scores = scale * q @ k^T per batch (4096x4096, K=512)
    bgemm_kernel<2><<<dim3(NHW / BN, NHW / BM, NB), 256>>>(
        qhi, qlo, khi, klo, nullptr, s, nullptr, nullptr, NHW, NC,
        tokStride, tokStride, scoStride, ATTN_SCALE);

    // 6) softmax -> attn hi/lo
    softmax4096_kernel<<<NB * NHW, 256>>>();

    // 7) o = attn @ (v^T)^T per batch (4096x512, K=4096) -> o hi/lo token-major
    bgemm_kernel<3><<<dim3(NC / BN, NHW / BM, NB), 256>>>(
        phi, plo, vthi, vtlo, nullptr, nullptr, ohi, olo, NC, NHW,
        scoStride, tokStride, tokStride, 1.f);

    // 8) o2 = o @ wo^T + bo (token-major fp32)
    bgemm_kernel<1><<<dim3(NC / BN, NTOK / BM), 256>>>(
        ohi, olo, whi + 3 * WSZ, wlo + 3 * WSZ, bo, o2, nullptr, nullptr, NC, NC, 0, 0, 0, 1.f);

    // 9) out = transpose(o2) + x
    final_kernel<<<dim3(NHW / 32, NC / 32, NB), dim3(32, 8)>>>(x, out);
}